// round 2
// baseline (speedup 1.0000x reference)
#include <cuda_runtime.h>
#include <cuda_bf16.h>
#include <stdint.h>

#define NROWS 8192
#define DDIM  256
#define BM 128
#define BN 128
#define BK 64
#define SSTR 72   // padded bf16 stride for conflict-free fragment loads

// ---------------- device scratch (no allocations allowed) ----------------
__device__ __nv_bfloat16 g_E[NROWS * DDIM];   // normalized embeds, bf16
__device__ float g_m[NROWS];                  // mean(e_i)
__device__ float g_a[NROWS];                  // mean(e_i^2) (== 1/D for normalized rows)
__device__ float g_irv[NROWS];                // 1 / (s - m^2)   (corr cancels in the ratio)
__device__ int   g_lab[NROWS];
__device__ double g_pos_sum, g_neg_sum, g_reg_sum;
__device__ unsigned long long g_pos_cnt, g_neg_cnt;
__device__ int g_is64;

// ---------------- init ----------------
__global__ void init_kernel() {
    g_pos_sum = 0.0; g_neg_sum = 0.0; g_reg_sum = 0.0;
    g_pos_cnt = 0ull; g_neg_cnt = 0ull;
}

// Detect whether labels buffer is int64 or int32.
// If int64 (values in [0,512)), every odd dword of the first 8192 dwords is 0.
// If int32, odd dwords are random labels; P(all 4096 are zero) ~ 0.
__global__ void detect_kernel(const unsigned int* __restrict__ lab) {
    __shared__ unsigned int any;
    if (threadIdx.x == 0) any = 0u;
    __syncthreads();
    unsigned int v = 0u;
    for (int i = threadIdx.x; i < NROWS / 2; i += blockDim.x)
        v |= lab[2 * i + 1];
    atomicOr(&any, v);
    __syncthreads();
    if (threadIdx.x == 0) g_is64 = (any == 0u) ? 1 : 0;
}

// ---------------- per-row normalize + stats ----------------
__global__ void prep_kernel(const float* __restrict__ x, const void* __restrict__ labp) {
    int row = blockIdx.x;
    int t = threadIdx.x;           // 256 threads == DDIM
    float v = x[(size_t)row * DDIM + t];
    float sx = v, sx2 = v * v;
#pragma unroll
    for (int o = 16; o; o >>= 1) {
        sx  += __shfl_xor_sync(0xffffffffu, sx, o);
        sx2 += __shfl_xor_sync(0xffffffffu, sx2, o);
    }
    __shared__ float a8[8], b8[8];
    if ((t & 31) == 0) { a8[t >> 5] = sx; b8[t >> 5] = sx2; }
    __syncthreads();
    if (t < 32) {
        float ax = (t < 8) ? a8[t] : 0.f;
        float bx = (t < 8) ? b8[t] : 0.f;
#pragma unroll
        for (int o = 4; o; o >>= 1) {
            ax += __shfl_xor_sync(0xffffffffu, ax, o);
            bx += __shfl_xor_sync(0xffffffffu, bx, o);
        }
        if (t == 0) { a8[0] = ax; b8[0] = bx; }
    }
    __syncthreads();
    float sumx = a8[0], sumx2 = b8[0];
    float norm = sqrtf(sumx2);
    float e = v / norm;
    g_E[(size_t)row * DDIM + t] = __float2bfloat16(e);
    if (t == 0) {
        float esum = sumx / norm;
        float m = esum * (1.0f / DDIM);
        float s = 1.0f / DDIM;            // mean(e^2) for a unit vector
        g_m[row] = m;
        g_a[row] = s;
        g_irv[row] = 1.0f / (s - m * m);
        int lv = g_is64 ? (int)(((const long long*)labp)[row])
                        : (((const int*)labp)[row]);
        g_lab[row] = lv;
        atomicAdd(&g_reg_sum, (double)fabsf(esum));
    }
}

// ---------------- bf16 mma.sync helper ----------------
__device__ __forceinline__ void mma16816(float* c, const uint32_t* a, const uint32_t* b) {
    asm volatile(
        "mma.sync.aligned.m16n8k16.row.col.f32.bf16.bf16.f32 "
        "{%0,%1,%2,%3}, {%4,%5,%6,%7}, {%8,%9}, {%0,%1,%2,%3};"
        : "+f"(c[0]), "+f"(c[1]), "+f"(c[2]), "+f"(c[3])
        : "r"(a[0]), "r"(a[1]), "r"(a[2]), "r"(a[3]), "r"(b[0]), "r"(b[1]));
}

// ---------------- fused GEMM (E * E^T) + SNR-dist epilogue ----------------
__global__ void __launch_bounds__(256, 1) gemm_kernel() {
    __shared__ __nv_bfloat16 sA[BM * SSTR];
    __shared__ __nv_bfloat16 sB[BN * SSTR];
    __shared__ float s_rm[BM], s_ra[BM], s_rirv[BM];
    __shared__ int   s_rl[BM];
    __shared__ float s_cm[BN], s_ca[BN];
    __shared__ int   s_cl[BN];
    __shared__ float rP[8], rN[8];
    __shared__ int   cP[8], cN[8];

    const int tid = threadIdx.x;
    const int bm = blockIdx.y, bn = blockIdx.x;
    const int i0 = bm * BM, j0 = bn * BN;

    // per-row / per-col parameters
    if (tid < BM) {
        int i = i0 + tid;
        s_rm[tid] = g_m[i]; s_ra[tid] = g_a[i]; s_rirv[tid] = g_irv[i]; s_rl[tid] = g_lab[i];
    } else {
        int j = j0 + (tid - BM);
        s_cm[tid - BM] = g_m[j]; s_ca[tid - BM] = g_a[j]; s_cl[tid - BM] = g_lab[j];
    }

    const int warp = tid >> 5, lane = tid & 31;
    const int wm = (warp & 1) * 64;        // warp row base within tile
    const int wn = (warp >> 1) * 32;       // warp col base within tile
    const int gid = lane >> 2, tig = lane & 3;

    float acc[4][4][4];
#pragma unroll
    for (int a = 0; a < 4; a++)
#pragma unroll
        for (int b = 0; b < 4; b++)
#pragma unroll
            for (int c = 0; c < 4; c++) acc[a][b][c] = 0.f;

    for (int k0 = 0; k0 < DDIM; k0 += BK) {
        __syncthreads();
        // cooperative load: 128 rows x 64 bf16 each for A and B
#pragma unroll
        for (int r = 0; r < 4; r++) {
            int idx = tid + r * 256;       // 0..1023
            int row = idx >> 3;
            int c8  = (idx & 7) * 8;
            uint4 va = *(const uint4*)(&g_E[(size_t)(i0 + row) * DDIM + k0 + c8]);
            *(uint4*)(&sA[row * SSTR + c8]) = va;
            uint4 vb = *(const uint4*)(&g_E[(size_t)(j0 + row) * DDIM + k0 + c8]);
            *(uint4*)(&sB[row * SSTR + c8]) = vb;
        }
        __syncthreads();

#pragma unroll
        for (int kk = 0; kk < BK; kk += 16) {
            uint32_t afr[4][4], bfr[4][2];
#pragma unroll
            for (int mi = 0; mi < 4; mi++) {
                int r0 = wm + mi * 16 + gid;
                afr[mi][0] = *(const uint32_t*)&sA[(r0)     * SSTR + kk +     tig * 2];
                afr[mi][1] = *(const uint32_t*)&sA[(r0 + 8) * SSTR + kk +     tig * 2];
                afr[mi][2] = *(const uint32_t*)&sA[(r0)     * SSTR + kk + 8 + tig * 2];
                afr[mi][3] = *(const uint32_t*)&sA[(r0 + 8) * SSTR + kk + 8 + tig * 2];
            }
#pragma unroll
            for (int ni = 0; ni < 4; ni++) {
                int c0 = wn + ni * 8 + gid;
                bfr[ni][0] = *(const uint32_t*)&sB[c0 * SSTR + kk +     tig * 2];
                bfr[ni][1] = *(const uint32_t*)&sB[c0 * SSTR + kk + 8 + tig * 2];
            }
#pragma unroll
            for (int mi = 0; mi < 4; mi++)
#pragma unroll
                for (int ni = 0; ni < 4; ni++)
                    mma16816(acc[mi][ni], afr[mi], bfr[ni]);
        }
    }
    __syncthreads();

    // ---------------- fused epilogue ----------------
    const float invD = 1.0f / DDIM;
    float psum = 0.f, nsum = 0.f;
    int pcnt = 0, ncnt = 0;
#pragma unroll
    for (int mi = 0; mi < 4; mi++) {
#pragma unroll
        for (int rr = 0; rr < 2; rr++) {
            int li = wm + mi * 16 + gid + rr * 8;
            float mi_v = s_rm[li], ai_v = s_ra[li], irv = s_rirv[li];
            int   lbi = s_rl[li];
            int   gi  = i0 + li;
#pragma unroll
            for (int ni = 0; ni < 4; ni++) {
#pragma unroll
                for (int cc = 0; cc < 2; cc++) {
                    int lj = wn + ni * 8 + tig * 2 + cc;
                    float dot = acc[mi][ni][rr * 2 + cc];
                    float md = mi_v - s_cm[lj];
                    float dist = (ai_v + s_ca[lj] - 2.f * dot * invD - md * md) * irv;
                    int gj = j0 + lj;
                    if (lbi == s_cl[lj]) {
                        if (gi != gj) {
                            float v = dist - 0.01f;
                            if (v > 0.f) { psum += v; pcnt++; }
                        }
                    } else {
                        float v = 0.2f - dist;
                        if (v > 0.f) { nsum += v; ncnt++; }
                    }
                }
            }
        }
    }

    // warp reduce
#pragma unroll
    for (int o = 16; o; o >>= 1) {
        psum += __shfl_xor_sync(0xffffffffu, psum, o);
        nsum += __shfl_xor_sync(0xffffffffu, nsum, o);
        pcnt += __shfl_xor_sync(0xffffffffu, pcnt, o);
        ncnt += __shfl_xor_sync(0xffffffffu, ncnt, o);
    }
    if (lane == 0) { rP[warp] = psum; rN[warp] = nsum; cP[warp] = pcnt; cN[warp] = ncnt; }
    __syncthreads();
    if (tid == 0) {
        float ps = 0.f, ns = 0.f; int pc = 0, nc = 0;
#pragma unroll
        for (int w = 0; w < 8; w++) { ps += rP[w]; ns += rN[w]; pc += cP[w]; nc += cN[w]; }
        if (ps != 0.f) atomicAdd(&g_pos_sum, (double)ps);
        if (ns != 0.f) atomicAdd(&g_neg_sum, (double)ns);
        if (pc) atomicAdd(&g_pos_cnt, (unsigned long long)pc);
        if (nc) atomicAdd(&g_neg_cnt, (unsigned long long)nc);
    }
}

// ---------------- finalize ----------------
__global__ void fin_kernel(float* out) {
    double pl = g_pos_sum / ((double)g_pos_cnt + 1e-12);
    double nl = g_neg_sum / ((double)g_neg_cnt + 1e-12);
    double reg = (g_reg_sum / (double)NROWS) * 0.1;
    out[0] = (float)(pl + nl + reg);
}

extern "C" void kernel_launch(void* const* d_in, const int* in_sizes, int n_in,
                              void* d_out, int out_size) {
    const float* embeds = (const float*)d_in[0];
    const void*  labels = (const void*)d_in[1];
    (void)in_sizes; (void)n_in; (void)out_size;

    init_kernel<<<1, 32>>>();
    detect_kernel<<<1, 256>>>((const unsigned int*)labels);
    prep_kernel<<<NROWS, DDIM>>>(embeds, labels);
    dim3 grid(NROWS / BN, NROWS / BM);
    gemm_kernel<<<grid, 256>>>();
    fin_kernel<<<1, 1>>>((float*)d_out);
}

// round 3
// speedup vs baseline: 1.5564x; 1.5564x over previous
#include <cuda_runtime.h>
#include <cuda_bf16.h>
#include <stdint.h>

#define NROWS 8192
#define DDIM  256
#define BM 128
#define BN 128
#define BK 64
#define SSTR 72   // padded bf16 stride: 144B = 9*16B -> 16B-aligned rows, conflict-spread
#define NKIT (DDIM / BK)   // 4
#define DSMEM_BYTES (4 * BM * SSTR * 2)   // 2 stages x (A+B) = 73728 B

// ---------------- device scratch ----------------
__device__ __nv_bfloat16 g_E[NROWS * DDIM];
__device__ float g_m[NROWS];
__device__ float g_a[NROWS];
__device__ float g_irv[NROWS];
__device__ int   g_lab[NROWS];
__device__ double g_pos_sum, g_neg_sum, g_reg_sum;
__device__ unsigned long long g_pos_cnt, g_neg_cnt;
__device__ int g_is64;

__global__ void init_kernel() {
    g_pos_sum = 0.0; g_neg_sum = 0.0; g_reg_sum = 0.0;
    g_pos_cnt = 0ull; g_neg_cnt = 0ull;
}

__global__ void detect_kernel(const unsigned int* __restrict__ lab) {
    __shared__ unsigned int any;
    if (threadIdx.x == 0) any = 0u;
    __syncthreads();
    unsigned int v = 0u;
    for (int i = threadIdx.x; i < NROWS / 2; i += blockDim.x)
        v |= lab[2 * i + 1];
    atomicOr(&any, v);
    __syncthreads();
    if (threadIdx.x == 0) g_is64 = (any == 0u) ? 1 : 0;
}

__global__ void prep_kernel(const float* __restrict__ x, const void* __restrict__ labp) {
    int row = blockIdx.x;
    int t = threadIdx.x;
    float v = x[(size_t)row * DDIM + t];
    float sx = v, sx2 = v * v;
#pragma unroll
    for (int o = 16; o; o >>= 1) {
        sx  += __shfl_xor_sync(0xffffffffu, sx, o);
        sx2 += __shfl_xor_sync(0xffffffffu, sx2, o);
    }
    __shared__ float a8[8], b8[8];
    if ((t & 31) == 0) { a8[t >> 5] = sx; b8[t >> 5] = sx2; }
    __syncthreads();
    if (t < 32) {
        float ax = (t < 8) ? a8[t] : 0.f;
        float bx = (t < 8) ? b8[t] : 0.f;
#pragma unroll
        for (int o = 4; o; o >>= 1) {
            ax += __shfl_xor_sync(0xffffffffu, ax, o);
            bx += __shfl_xor_sync(0xffffffffu, bx, o);
        }
        if (t == 0) { a8[0] = ax; b8[0] = bx; }
    }
    __syncthreads();
    float sumx = a8[0], sumx2 = b8[0];
    float norm = sqrtf(sumx2);
    float e = v / norm;
    g_E[(size_t)row * DDIM + t] = __float2bfloat16(e);
    if (t == 0) {
        float esum = sumx / norm;
        float m = esum * (1.0f / DDIM);
        float s = 1.0f / DDIM;
        g_m[row] = m;
        g_a[row] = s;
        g_irv[row] = 1.0f / (s - m * m);
        int lv = g_is64 ? (int)(((const long long*)labp)[row])
                        : (((const int*)labp)[row]);
        g_lab[row] = lv;
        atomicAdd(&g_reg_sum, (double)fabsf(esum));
    }
}

// ---------------- asm helpers ----------------
__device__ __forceinline__ void mma16816(float* c, const uint32_t* a, const uint32_t* b) {
    asm volatile(
        "mma.sync.aligned.m16n8k16.row.col.f32.bf16.bf16.f32 "
        "{%0,%1,%2,%3}, {%4,%5,%6,%7}, {%8,%9}, {%0,%1,%2,%3};"
        : "+f"(c[0]), "+f"(c[1]), "+f"(c[2]), "+f"(c[3])
        : "r"(a[0]), "r"(a[1]), "r"(a[2]), "r"(a[3]), "r"(b[0]), "r"(b[1]));
}
__device__ __forceinline__ void ldsm_x4(uint32_t& r0, uint32_t& r1, uint32_t& r2, uint32_t& r3, uint32_t addr) {
    asm volatile("ldmatrix.sync.aligned.m8n8.x4.shared.b16 {%0,%1,%2,%3}, [%4];"
                 : "=r"(r0), "=r"(r1), "=r"(r2), "=r"(r3) : "r"(addr));
}
__device__ __forceinline__ void cp16(uint32_t dst, const void* src) {
    asm volatile("cp.async.cg.shared.global [%0], [%1], 16;" :: "r"(dst), "l"(src));
}
#define CP_COMMIT() asm volatile("cp.async.commit_group;")
#define CP_WAIT(n)  asm volatile("cp.async.wait_group %0;" :: "n"(n))

// ---------------- fused triangular GEMM + epilogue ----------------
__global__ void __launch_bounds__(256, 1) gemm_kernel() {
    extern __shared__ __nv_bfloat16 dsm[];
    __shared__ float s_rm[BM], s_ra[BM], s_rirv[BM];
    __shared__ int   s_rl[BM];
    __shared__ float s_cm[BN], s_ca[BN], s_cirv[BN];
    __shared__ int   s_cl[BN];
    __shared__ float rP[8], rN[8];
    __shared__ int   cP[8], cN[8];

    const int tid = threadIdx.x;

    // triangular block decode: bm >= bn
    int kblk = blockIdx.x;
    int bm = (int)((sqrtf(8.f * (float)kblk + 1.f) - 1.f) * 0.5f);
    while ((bm + 1) * (bm + 2) / 2 <= kblk) bm++;
    while (bm * (bm + 1) / 2 > kblk) bm--;
    int bn = kblk - bm * (bm + 1) / 2;
    const int i0 = bm * BM, j0 = bn * BN;
    const bool offdiag = (bm != bn);

    if (tid < BM) {
        int i = i0 + tid;
        s_rm[tid] = g_m[i]; s_ra[tid] = g_a[i]; s_rirv[tid] = g_irv[i]; s_rl[tid] = g_lab[i];
    } else {
        int j = j0 + (tid - BM);
        s_cm[tid - BM] = g_m[j]; s_ca[tid - BM] = g_a[j];
        s_cirv[tid - BM] = g_irv[j]; s_cl[tid - BM] = g_lab[j];
    }

    const int warp = tid >> 5, lane = tid & 31;
    const int wm = (warp & 1) * 64;
    const int wn = (warp >> 1) * 32;
    const int gid = lane >> 2, tig = lane & 3;

    uint32_t smem_u32 = (uint32_t)__cvta_generic_to_shared(dsm);
    const int stageElems = BM * SSTR;

    float acc[4][4][4];
#pragma unroll
    for (int a = 0; a < 4; a++)
#pragma unroll
        for (int b = 0; b < 4; b++)
#pragma unroll
            for (int c = 0; c < 4; c++) acc[a][b][c] = 0.f;

    // per-thread load geometry: 4 chunks for A, 4 for B per stage
    const int lrow = tid >> 3;               // 0..31 (stride 32 across r)
    const int lc8  = (tid & 7) * 8;

    // issue loads for stage s, k-offset k0
    auto issue = [&](int s, int k0) {
        uint32_t baseA = smem_u32 + (uint32_t)(s * stageElems) * 2u;
        uint32_t baseB = smem_u32 + (uint32_t)((2 + s) * stageElems) * 2u;
#pragma unroll
        for (int r = 0; r < 4; r++) {
            int row = lrow + r * 32;
            uint32_t off = (uint32_t)(row * SSTR + lc8) * 2u;
            cp16(baseA + off, &g_E[(size_t)(i0 + row) * DDIM + k0 + lc8]);
            cp16(baseB + off, &g_E[(size_t)(j0 + row) * DDIM + k0 + lc8]);
        }
    };

    issue(0, 0);
    CP_COMMIT();

    for (int it = 0; it < NKIT; it++) {
        if (it + 1 < NKIT) {
            issue((it + 1) & 1, (it + 1) * BK);
            CP_COMMIT();
            CP_WAIT(1);
        } else {
            CP_WAIT(0);
        }
        __syncthreads();

        int s = it & 1;
        uint32_t aBase = smem_u32 + (uint32_t)(s * stageElems) * 2u;
        uint32_t bBase = smem_u32 + (uint32_t)((2 + s) * stageElems) * 2u;

#pragma unroll
        for (int kk = 0; kk < BK; kk += 16) {
            uint32_t afr[4][4], bfr[4][2];
#pragma unroll
            for (int mi = 0; mi < 4; mi++) {
                int row = wm + mi * 16 + (lane & 15);
                int ko  = kk + ((lane >> 4) << 3);
                uint32_t addr = aBase + (uint32_t)(row * SSTR + ko) * 2u;
                ldsm_x4(afr[mi][0], afr[mi][1], afr[mi][2], afr[mi][3], addr);
            }
#pragma unroll
            for (int p = 0; p < 2; p++) {
                int col = wn + p * 16 + ((lane >> 4) << 3) + (lane & 7);
                int ko  = kk + (((lane >> 3) & 1) << 3);
                uint32_t addr = bBase + (uint32_t)(col * SSTR + ko) * 2u;
                ldsm_x4(bfr[2 * p][0], bfr[2 * p][1], bfr[2 * p + 1][0], bfr[2 * p + 1][1], addr);
            }
#pragma unroll
            for (int mi = 0; mi < 4; mi++)
#pragma unroll
                for (int ni = 0; ni < 4; ni++)
                    mma16816(acc[mi][ni], afr[mi], bfr[ni]);
        }
        __syncthreads();
    }

    // ---------------- epilogue: both orientations for off-diagonal blocks ----------------
    const float invD = 1.0f / DDIM;
    float psum = 0.f, nsum = 0.f;
    int pcnt = 0, ncnt = 0;
#pragma unroll
    for (int mi = 0; mi < 4; mi++) {
#pragma unroll
        for (int rr = 0; rr < 2; rr++) {
            int li = wm + mi * 16 + gid + rr * 8;
            float mi_v = s_rm[li], ai_v = s_ra[li], irv_i = s_rirv[li];
            int   lbi = s_rl[li];
            int   gi  = i0 + li;
#pragma unroll
            for (int ni = 0; ni < 4; ni++) {
#pragma unroll
                for (int cc = 0; cc < 2; cc++) {
                    int lj = wn + ni * 8 + tig * 2 + cc;
                    float dot = acc[mi][ni][rr * 2 + cc];
                    float md = mi_v - s_cm[lj];
                    float num = ai_v + s_ca[lj] - 2.f * dot * invD - md * md;
                    int gj = j0 + lj;
                    bool same = (lbi == s_cl[lj]);
                    // orientation (i, j), anchor i
                    {
                        float dist = num * irv_i;
                        if (same) {
                            if (gi != gj) {
                                float v = dist - 0.01f;
                                if (v > 0.f) { psum += v; pcnt++; }
                            }
                        } else {
                            float v = 0.2f - dist;
                            if (v > 0.f) { nsum += v; ncnt++; }
                        }
                    }
                    // orientation (j, i), anchor j (off-diagonal blocks: i != j always)
                    if (offdiag) {
                        float dist = num * s_cirv[lj];
                        if (same) {
                            float v = dist - 0.01f;
                            if (v > 0.f) { psum += v; pcnt++; }
                        } else {
                            float v = 0.2f - dist;
                            if (v > 0.f) { nsum += v; ncnt++; }
                        }
                    }
                }
            }
        }
    }

#pragma unroll
    for (int o = 16; o; o >>= 1) {
        psum += __shfl_xor_sync(0xffffffffu, psum, o);
        nsum += __shfl_xor_sync(0xffffffffu, nsum, o);
        pcnt += __shfl_xor_sync(0xffffffffu, pcnt, o);
        ncnt += __shfl_xor_sync(0xffffffffu, ncnt, o);
    }
    if (lane == 0) { rP[warp] = psum; rN[warp] = nsum; cP[warp] = pcnt; cN[warp] = ncnt; }
    __syncthreads();
    if (tid == 0) {
        float ps = 0.f, ns = 0.f; int pc = 0, nc = 0;
#pragma unroll
        for (int w = 0; w < 8; w++) { ps += rP[w]; ns += rN[w]; pc += cP[w]; nc += cN[w]; }
        if (ps != 0.f) atomicAdd(&g_pos_sum, (double)ps);
        if (ns != 0.f) atomicAdd(&g_neg_sum, (double)ns);
        if (pc) atomicAdd(&g_pos_cnt, (unsigned long long)pc);
        if (nc) atomicAdd(&g_neg_cnt, (unsigned long long)nc);
    }
}

__global__ void fin_kernel(float* out) {
    double pl = g_pos_sum / ((double)g_pos_cnt + 1e-12);
    double nl = g_neg_sum / ((double)g_neg_cnt + 1e-12);
    double reg = (g_reg_sum / (double)NROWS) * 0.1;
    out[0] = (float)(pl + nl + reg);
}

extern "C" void kernel_launch(void* const* d_in, const int* in_sizes, int n_in,
                              void* d_out, int out_size) {
    const float* embeds = (const float*)d_in[0];
    const void*  labels = (const void*)d_in[1];
    (void)in_sizes; (void)n_in; (void)out_size;

    static int attr_done = 0;
    if (!attr_done) {
        cudaFuncSetAttribute(gemm_kernel, cudaFuncAttributeMaxDynamicSharedMemorySize, DSMEM_BYTES);
        attr_done = 1;
    }

    init_kernel<<<1, 32>>>();
    detect_kernel<<<1, 256>>>((const unsigned int*)labels);
    prep_kernel<<<NROWS, DDIM>>>(embeds, labels);
    const int nblk = (NROWS / BM) * (NROWS / BM + 1) / 2;   // 2080
    gemm_kernel<<<nblk, 256, DSMEM_BYTES>>>();
    fin_kernel<<<1, 1>>>((float*)d_out);
}